// round 4
// baseline (speedup 1.0000x reference)
#include <cuda_runtime.h>
#include <math.h>

#define TWO_PI 6.283185307179586f
#define EPS 1e-6f
#define NEG_HALF_LOG2E (-0.7213475204444817f)
#define BD 320

typedef unsigned long long u64;

// ---------------- device scratch (double-buffered across layers) ----------------
#define MAXS 4096
#define MAXROWS 320

__device__ float g_SWb[2][MAXS], g_SPXb[2][MAXS], g_SPYb[2][MAXS];
__device__ float g_SC00b[2][MAXS], g_SC01b[2][MAXS], g_SC10b[2][MAXS], g_SC11b[2][MAXS];
__device__ float g_TOTb[2][MAXROWS];
__device__ float g_SIG[MAXROWS];

__device__ __forceinline__ float fast_exp2(float x) {
    float y;
    asm("ex2.approx.ftz.f32 %0, %1;" : "=f"(y) : "f"(x));
    return y;
}

// ---- packed f32x2 helpers (sm_103a FFMA2 path, PTX-only) ----
__device__ __forceinline__ u64 pk2(float lo, float hi) {
    u64 r; asm("mov.b64 %0, {%1, %2};" : "=l"(r) : "f"(lo), "f"(hi)); return r;
}
__device__ __forceinline__ void upk2(u64 v, float& lo, float& hi) {
    asm("mov.b64 {%0, %1}, %2;" : "=f"(lo), "=f"(hi) : "l"(v));
}
__device__ __forceinline__ u64 add2(u64 a, u64 b) {
    u64 r; asm("add.rn.f32x2 %0, %1, %2;" : "=l"(r) : "l"(a), "l"(b)); return r;
}
__device__ __forceinline__ u64 mul2(u64 a, u64 b) {
    u64 r; asm("mul.rn.f32x2 %0, %1, %2;" : "=l"(r) : "l"(a), "l"(b)); return r;
}
__device__ __forceinline__ u64 fma2(u64 a, u64 b, u64 c) {
    u64 r; asm("fma.rn.f32x2 %0, %1, %2, %3;" : "=l"(r) : "l"(a), "l"(b), "l"(c)); return r;
}

// ================= fused layer kernel: one block per output row (b, lo) ==========
// phases: stage kernel+data (w/ bn scale) -> conv into shared eval tile
//         -> f32x2 eval + relu scale -> u64-key rank select -> scatter + row sums
__global__ __launch_bounds__(BD) void k_layer(
    const float* __restrict__ in_x, const float* __restrict__ kern,
    const float* __restrict__ bias,
    int Li, int Nd, int Lo, int Nk, int N, int nsel,
    int first, int compute_sig, int isel, int osel)
{
    extern __shared__ __align__(16) char smem_raw[];
    const int tid = threadIdx.x;
    const int row = blockIdx.x;
    const int b = row / Lo, lo = row % Lo;
    const int Npad = (N + 1) & ~1;
    const int LiNd = Li * Nd, LiNk = Li * Nk;

    u64*   sKey = (u64*)smem_raw;              // Npad keys
    float* sAf  = (float*)(sKey + Npad);       // 2*Npad: (px,px,py,py) pairs
    float* sBf  = sAf + 2 * Npad;              // (ea,ea,eb,eb)
    float* sCf  = sBf + 2 * Npad;              // (ec,ec,w,w)
    float* sd   = sCf + 2 * Npad;              // 7*LiNd staged data
    float* skn  = sd + 7 * LiNd;               // 7*LiNk staged kernel
    float* s_scl = skn + 7 * LiNk;             // 16
    float* s_red = s_scl + 16;                 // 256
    float* s_out = s_red + 256;                // 64: |I| per rank, I per rank

    float *sd_w = sd, *sd_px = sd + LiNd, *sd_py = sd + 2 * LiNd;
    float *sd_c00 = sd + 3 * LiNd, *sd_c01 = sd + 4 * LiNd, *sd_c10 = sd + 5 * LiNd, *sd_c11 = sd + 6 * LiNd;
    float *sk_w = skn, *sk_px = skn + LiNk, *sk_py = skn + 2 * LiNk;
    float *sk_c00 = skn + 3 * LiNk, *sk_c01 = skn + 4 * LiNk, *sk_c10 = skn + 5 * LiNk, *sk_c11 = skn + 6 * LiNk;

    // ---- stage kernel params for this lo ----
    for (int i = tid; i < LiNk; i += BD) {
        const float* kp = kern + ((lo * Li + i / Nk) * Nk + (i % Nk)) * 7;
        sk_w[i] = kp[0]; sk_px[i] = kp[1]; sk_py[i] = kp[2];
        sk_c00[i] = kp[3]; sk_c01[i] = kp[4]; sk_c10[i] = kp[5]; sk_c11[i] = kp[6];
    }

    // ---- stage data mixture with batchnorm scaling ----
    if (first) {
        // per_gaussian=True bn on raw input (Li=1, Nd=64)
        if (tid < 64) {
            const float* m = in_x + (b * 64 + tid) * 7;
            float w = m[0], c00 = m[3], c01 = m[4], c10 = m[5], c11 = m[6];
            sd_w[tid] = w; sd_px[tid] = m[1]; sd_py[tid] = m[2];
            sd_c00[tid] = c00; sd_c01[tid] = c01; sd_c10[tid] = c10; sd_c11[tid] = c11;
            float det = c00 * c11 - c01 * c10;
            s_red[tid] = fabsf(w * TWO_PI * sqrtf(fmaxf(det, EPS)));
        }
        __syncthreads();
        if (tid < 32) {
            float v = s_red[tid] + s_red[tid + 32];
            for (int o = 16; o > 0; o >>= 1) v += __shfl_xor_sync(0xffffffffu, v, o);
            if (tid == 0) s_scl[0] = 1.0f / (v + EPS);
        }
        __syncthreads();
        if (tid < 64) sd_w[tid] *= s_scl[0];
    } else {
        // per_gaussian=False bn: scale per li from mean-over-batch of prev-layer tot
        if (tid < Li * 32) {
            int li = tid >> 5, bb = tid & 31;
            s_red[tid] = g_TOTb[isel][bb * Li + li];
        }
        __syncthreads();
        if (tid < Li) {
            float s = 0.0f;
            for (int j = 0; j < 32; j++) s += s_red[tid * 32 + j];
            s_scl[tid] = 1.0f / (s * (1.0f / 32.0f) + EPS);
        }
        __syncthreads();
        for (int i = tid; i < LiNd; i += BD) {
            int li = i / Nd;
            int src = b * LiNd + i;
            sd_w[i]   = g_SWb[isel][src] * s_scl[li];
            sd_px[i]  = g_SPXb[isel][src]; sd_py[i]  = g_SPYb[isel][src];
            sd_c00[i] = g_SC00b[isel][src]; sd_c01[i] = g_SC01b[isel][src];
            sd_c10[i] = g_SC10b[isel][src]; sd_c11[i] = g_SC11b[isel][src];
        }
    }
    __syncthreads();

    // ---- conv phase: build pair-interleaved eval tile in shared ----
    for (int i = tid; i < Npad; i += BD) {
        float psx = 0, psy = 0, ea = 0, eb = 0, ec = 0, ws = 0;
        if (i < N) {
            int nk = i % Nk; int di = i / Nk; int li = di / Nd;
            int ki = li * Nk + nk;
            float d00 = sd_c00[di], d01 = sd_c01[di], d10 = sd_c10[di], d11 = sd_c11[di];
            float k00 = sk_c00[ki], k01 = sk_c01[ki], k10 = sk_c10[ki], k11 = sk_c11[ki];
            float s00 = d00 + k00, s01 = d01 + k01, s10 = d10 + k10, s11 = d11 + k11;
            float dd = d00 * d11 - d01 * d10;
            float dk = k00 * k11 - k01 * k10;
            float ds = s00 * s11 - s01 * s10;
            ws = sd_w[di] * sk_w[ki] * TWO_PI * sqrtf(dd * dk / fmaxf(ds, EPS));
            psx = sd_px[di] + sk_px[ki]; psy = sd_py[di] + sk_py[ki];
            float inv = 1.0f / ds;
            ea = NEG_HALF_LOG2E * s11 * inv;
            eb = -NEG_HALF_LOG2E * (s01 + s10) * inv;
            ec = NEG_HALF_LOG2E * s00 * inv;
        } else {
            sKey[i] = 0ull;  // pad key: never outranks real keys
        }
        int j4 = (i >> 1) * 4 + (i & 1);
        sAf[j4] = psx; sAf[j4 + 2] = psy;
        sBf[j4] = ea;  sBf[j4 + 2] = eb;
        sCf[j4] = ec;  sCf[j4 + 2] = ws;
    }
    __syncthreads();

    // ---- eval phase (f32x2 packed) ----
    float myw2[2] = {0.0f, 0.0f};
    int nc = 0;
    float bs = bias[lo];
    int half = Npad >> 1;
    const float4* sA = (const float4*)sAf;
    const float4* sB = (const float4*)sBf;
    const float4* sC = (const float4*)sCf;

    for (int k = tid; k < N; k += BD) {
        int k4 = (k >> 1) * 4 + (k & 1);
        float kx = sAf[k4], ky = sAf[k4 + 2], wsk = sCf[k4 + 2];
        u64 nkx2 = pk2(-kx, -kx);
        u64 nky2 = pk2(-ky, -ky);
        u64 acc = 0ull;
        #pragma unroll 4
        for (int j = 0; j < half; j++) {
            float4 a = sA[j];
            float4 bq = sB[j];
            float4 c = sC[j];
            u64 px2 = *(const u64*)&a.x;  u64 py2 = *(const u64*)&a.z;
            u64 ea2 = *(const u64*)&bq.x; u64 eb2 = *(const u64*)&bq.z;
            u64 ec2 = *(const u64*)&c.x;  u64 w2p = *(const u64*)&c.z;
            u64 dx = add2(px2, nkx2);
            u64 dy = add2(py2, nky2);
            u64 u  = fma2(ea2, dx, mul2(eb2, dy));
            u64 md = fma2(dx, u, mul2(mul2(ec2, dy), dy));
            float m0, m1; upk2(md, m0, m1);
            u64 e = pk2(fast_exp2(m0), fast_exp2(m1));
            acc = fma2(w2p, e, acc);
        }
        float a0, a1; upk2(acc, a0, a1);
        float v = a0 + a1 + bs;
        float scale = fmaxf(v, 0.0f) / (fabsf(v) + EPS);
        float w2 = wsk * scale;
        myw2[nc++] = w2;
        sKey[k] = ((u64)__float_as_uint(fabsf(w2)) << 32) | (u64)(unsigned)(~(unsigned)k);
    }
    __syncthreads();

    // ---- rank select + scatter ----
    int nq = Npad >> 1;
    const ulonglong2* K2 = (const ulonglong2*)sKey;
    for (int c = 0; c < nc; c++) {
        int k = tid + c * BD;
        u64 mykey = sKey[k];
        int rank = 0;
        #pragma unroll 8
        for (int j = 0; j < nq; j++) {
            ulonglong2 q = K2[j];
            rank += (int)(q.x > mykey) + (int)(q.y > mykey);
        }
        if (rank < nsel) {
            int nk = k % Nk; int di = k / Nk; int li = di / Nd;
            int ki = li * Nk + nk;
            float c00 = sd_c00[di] + sk_c00[ki];
            float c01 = sd_c01[di] + sk_c01[ki];
            float c10 = sd_c10[di] + sk_c10[ki];
            float c11 = sd_c11[di] + sk_c11[ki];
            int k4 = (k >> 1) * 4 + (k & 1);
            int dst = row * nsel + rank;
            float w2 = myw2[c];
            g_SWb[osel][dst] = w2;
            g_SPXb[osel][dst] = sAf[k4]; g_SPYb[osel][dst] = sAf[k4 + 2];
            g_SC00b[osel][dst] = c00; g_SC01b[osel][dst] = c01;
            g_SC10b[osel][dst] = c10; g_SC11b[osel][dst] = c11;
            float I = w2 * TWO_PI * sqrtf(fmaxf(c00 * c11 - c01 * c10, EPS));
            s_out[rank] = fabsf(I);
            s_out[32 + rank] = I;
        }
    }
    __syncthreads();
    if (tid == 0) {
        float tot = 0.0f, sg = 0.0f;
        for (int t = 0; t < nsel; t++) { tot += s_out[t]; sg += s_out[32 + t]; }
        g_TOTb[osel][row] = tot;
        if (compute_sig) g_SIG[row] = sg;
    }
}

// ---------------- final: batchnorm + integrate + log_softmax ----------------
__global__ void k_final(float* __restrict__ out) {
    int tid = threadIdx.x; // 0..319
    __shared__ float scl[10];
    __shared__ float logit[320];
    if (tid < 10) {
        float t = 0.0f;
        for (int b = 0; b < 32; b++) t += g_TOTb[0][b * 10 + tid];
        scl[tid] = 1.0f / (t / 32.0f + EPS);
    }
    __syncthreads();
    logit[tid] = g_SIG[tid] * scl[tid % 10];
    __syncthreads();
    if (tid < 32) {
        int b = tid;
        float mx = -INFINITY;
        for (int l = 0; l < 10; l++) mx = fmaxf(mx, logit[b * 10 + l]);
        float se = 0.0f;
        for (int l = 0; l < 10; l++) se += expf(logit[b * 10 + l] - mx);
        float lse = mx + logf(se);
        for (int l = 0; l < 10; l++) out[b * 10 + l] = logit[b * 10 + l] - lse;
    }
}

static inline int smem_bytes(int N, int LiNd, int LiNk) {
    int Npad = (N + 1) & ~1;
    return Npad * 8 + 4 * (6 * Npad + 7 * (LiNd + LiNk) + 16 + 256 + 64);
}

extern "C" void kernel_launch(void* const* d_in, const int* in_sizes, int n_in,
                              void* d_out, int out_size) {
    const float* in_x = (const float*)d_in[0];
    const float* k1 = (const float*)d_in[1];
    const float* k2 = (const float*)d_in[2];
    const float* k3 = (const float*)d_in[3];
    const float* b1 = (const float*)d_in[4];
    const float* b2 = (const float*)d_in[5];
    const float* b3 = (const float*)d_in[6];
    float* out = (float*)d_out;

    // layer 1: Li=1, Nd=64, Lo=5, Nk=5, N=320, nsel=25 -> buf 0
    k_layer<<<160, BD, smem_bytes(320, 64, 5)>>>(
        in_x, k1, b1, 1, 64, 5, 5, 320, 25, 1, 0, 0, 0);

    // layer 2: Li=5, Nd=25, Lo=6, Nk=5, N=625, nsel=12 -> buf 1
    k_layer<<<192, BD, smem_bytes(625, 125, 25)>>>(
        in_x, k2, b2, 5, 25, 6, 5, 625, 12, 0, 0, 0, 1);

    // layer 3: Li=6, Nd=12, Lo=10, Nk=5, N=360, nsel=5 -> buf 0, writes sig
    k_layer<<<320, BD, smem_bytes(360, 72, 30)>>>(
        in_x, k3, b3, 6, 12, 10, 5, 360, 5, 0, 1, 1, 0);

    k_final<<<1, 320>>>(out);
}

// round 5
// speedup vs baseline: 1.4787x; 1.4787x over previous
#include <cuda_runtime.h>
#include <math.h>

#define TWO_PI 6.283185307179586f
#define EPS 1e-6f
#define NEG_HALF_LOG2E (-0.7213475204444817f)

typedef unsigned long long u64;

// ---------------- device scratch ----------------
#define MAXM 120000
#define MAXS 4096
#define MAXROWS 320

__device__ float g_W[MAXM], g_PX[MAXM], g_PY[MAXM];
__device__ float g_C00[MAXM], g_C01[MAXM], g_C10[MAXM], g_C11[MAXM];
__device__ float g_EA[MAXM], g_EB[MAXM], g_EC[MAXM];
__device__ float g_W2[MAXM];

__device__ float g_SW[MAXS], g_SPX[MAXS], g_SPY[MAXS];
__device__ float g_SC00[MAXS], g_SC01[MAXS], g_SC10[MAXS], g_SC11[MAXS];

__device__ float g_TOT[MAXROWS], g_SIG[MAXROWS];
__device__ int g_tick = 0;

__device__ __forceinline__ float fast_exp2(float x) {
    float y; asm("ex2.approx.ftz.f32 %0, %1;" : "=f"(y) : "f"(x)); return y;
}
__device__ __forceinline__ float fast_sqrt(float x) {
    float y; asm("sqrt.approx.ftz.f32 %0, %1;" : "=f"(y) : "f"(x)); return y;
}
__device__ __forceinline__ float fast_rcp(float x) {
    float y; asm("rcp.approx.ftz.f32 %0, %1;" : "=f"(y) : "f"(x)); return y;
}

// ---- packed f32x2 helpers ----
__device__ __forceinline__ u64 pk2(float lo, float hi) {
    u64 r; asm("mov.b64 %0, {%1, %2};" : "=l"(r) : "f"(lo), "f"(hi)); return r;
}
__device__ __forceinline__ void upk2(u64 v, float& lo, float& hi) {
    asm("mov.b64 {%0, %1}, %2;" : "=f"(lo), "=f"(hi) : "l"(v));
}
__device__ __forceinline__ u64 add2(u64 a, u64 b) {
    u64 r; asm("add.rn.f32x2 %0, %1, %2;" : "=l"(r) : "l"(a), "l"(b)); return r;
}
__device__ __forceinline__ u64 mul2(u64 a, u64 b) {
    u64 r; asm("mul.rn.f32x2 %0, %1, %2;" : "=l"(r) : "l"(a), "l"(b)); return r;
}
__device__ __forceinline__ u64 fma2(u64 a, u64 b, u64 c) {
    u64 r; asm("fma.rn.f32x2 %0, %1, %2, %3;" : "=l"(r) : "l"(a), "l"(b), "l"(c)); return r;
}

// ---------------- K1: batchnorm(per_gaussian=True) on input ----------------
__global__ void k_bn_input(const float* __restrict__ in_x) {
    int b = blockIdx.x;
    int n = threadIdx.x; // 0..63
    const float* m = in_x + (b * 64 + n) * 7;
    float w = m[0], px = m[1], py = m[2];
    float c00 = m[3], c01 = m[4], c10 = m[5], c11 = m[6];
    float det = c00 * c11 - c01 * c10;
    float I = w * TWO_PI * fast_sqrt(fmaxf(det, EPS));

    __shared__ float sh[64];
    sh[n] = fabsf(I);
    __syncthreads();
    for (int s = 32; s > 0; s >>= 1) {
        if (n < s) sh[n] += sh[n + s];
        __syncthreads();
    }
    float tot = sh[0];

    int idx = b * 64 + n;
    g_SW[idx]   = w / (tot + EPS);
    g_SPX[idx]  = px;  g_SPY[idx]  = py;
    g_SC00[idx] = c00; g_SC01[idx] = c01;
    g_SC10[idx] = c10; g_SC11[idx] = c11;
}

// ---------------- conv ----------------
__global__ void k_conv(const float* __restrict__ kern,
                       int B, int Li, int Nd, int Lo, int Nk) {
    int total = B * Lo * Li * Nd * Nk;
    int i = blockIdx.x * blockDim.x + threadIdx.x;
    if (i >= total) return;
    int nk = i % Nk; int t = i / Nk;
    int nd = t % Nd; t /= Nd;
    int li = t % Li; t /= Li;
    int lo = t % Lo; int b = t / Lo;

    int di = (b * Li + li) * Nd + nd;
    float wd = g_SW[di], pdx = g_SPX[di], pdy = g_SPY[di];
    float d00 = g_SC00[di], d01 = g_SC01[di], d10 = g_SC10[di], d11 = g_SC11[di];

    const float* kp = kern + (((lo * Li + li) * Nk) + nk) * 7;
    float wk = kp[0], pkx = kp[1], pky = kp[2];
    float k00 = kp[3], k01 = kp[4], k10 = kp[5], k11 = kp[6];

    float s00 = d00 + k00, s01 = d01 + k01, s10 = d10 + k10, s11 = d11 + k11;
    float dd = d00 * d11 - d01 * d10;
    float dk = k00 * k11 - k01 * k10;
    float ds = s00 * s11 - s01 * s10;
    float inv = fast_rcp(fmaxf(ds, EPS));
    float ws = wd * wk * TWO_PI * fast_sqrt(dd * dk * inv);

    int o = (b * Lo + lo) * (Li * Nd * Nk) + (li * Nd + nd) * Nk + nk;
    g_W[o] = ws;
    g_PX[o] = pdx + pkx; g_PY[o] = pdy + pky;
    g_C00[o] = s00; g_C01[o] = s01; g_C10[o] = s10; g_C11[o] = s11;

    g_EA[o] = NEG_HALF_LOG2E * s11 * inv;
    g_EB[o] = -NEG_HALF_LOG2E * (s01 + s10) * inv;
    g_EC[o] = NEG_HALF_LOG2E * s00 * inv;
}

// ---------------- eval_at_centers + relu scaling (f32x2 packed) ----------------
__global__ void k_eval(int N, int Lo, const float* __restrict__ bias) {
    extern __shared__ __align__(16) float sh[];
    int Np = (N + 1) & ~1;
    int half = Np >> 1;
    float* sAf = sh;
    float* sBf = sh + 2 * Np;
    float* sCf = sh + 4 * Np;

    int row = blockIdx.y;
    int base = row * N;
    for (int n = threadIdx.x; n < Np; n += blockDim.x) {
        int j4 = (n >> 1) * 4 + (n & 1);
        if (n < N) {
            int g = base + n;
            sAf[j4] = g_PX[g]; sAf[j4 + 2] = g_PY[g];
            sBf[j4] = g_EA[g]; sBf[j4 + 2] = g_EB[g];
            sCf[j4] = g_EC[g]; sCf[j4 + 2] = g_W[g];
        } else {
            sAf[j4] = 0.0f; sAf[j4 + 2] = 0.0f;
            sBf[j4] = 0.0f; sBf[j4 + 2] = 0.0f;
            sCf[j4] = 0.0f; sCf[j4 + 2] = 0.0f;
        }
    }
    __syncthreads();

    int k = blockIdx.x * blockDim.x + threadIdx.x;
    if (k >= N) return;

    int k4 = (k >> 1) * 4 + (k & 1);
    float kx = sAf[k4], ky = sAf[k4 + 2];
    float wk = sCf[k4 + 2];
    u64 nkx2 = pk2(-kx, -kx);
    u64 nky2 = pk2(-ky, -ky);
    u64 acc = 0ull;

    const float4* sA = (const float4*)sAf;
    const float4* sB = (const float4*)sBf;
    const float4* sC = (const float4*)sCf;

    #pragma unroll 4
    for (int j = 0; j < half; j++) {
        float4 a = sA[j];
        float4 bq = sB[j];
        float4 c = sC[j];
        u64 px2 = *(const u64*)&a.x;  u64 py2 = *(const u64*)&a.z;
        u64 ea2 = *(const u64*)&bq.x; u64 eb2 = *(const u64*)&bq.z;
        u64 ec2 = *(const u64*)&c.x;  u64 w2p = *(const u64*)&c.z;

        u64 dx = add2(px2, nkx2);
        u64 dy = add2(py2, nky2);
        u64 u  = fma2(ea2, dx, mul2(eb2, dy));
        u64 md = fma2(dx, u, mul2(mul2(ec2, dy), dy));
        float m0, m1; upk2(md, m0, m1);
        u64 e = pk2(fast_exp2(m0), fast_exp2(m1));
        acc = fma2(w2p, e, acc);
    }

    float a0, a1; upk2(acc, a0, a1);
    float v = a0 + a1 + bias[row % Lo];
    float scale = fmaxf(v, 0.0f) * fast_rcp(fabsf(v) + EPS);
    g_W2[base + k] = wk * scale;
}

// ---------------- rank-based top-k: one block per row, 256 threads ----------------
// key = (|w2| bits << 32) | ~k  -> unique; descending key order == jax top_k order.
// rank (= #keys greater) is the output slot. Layer 3 also runs the fused finale.
__global__ void k_topk(int N, int nsel, int do_final, int rows, float* __restrict__ out) {
    const int tid = threadIdx.x;
    const int row = blockIdx.x;
    const int base = row * N;
    const int Np = (N + 1) & ~1;

    __shared__ __align__(16) u64 keys[640];
    __shared__ float s_out[64];
    __shared__ int s_last;
    __shared__ float scl[10];
    __shared__ float logit[320];

    for (int n = tid; n < Np; n += 256) {
        keys[n] = (n < N)
            ? (((u64)__float_as_uint(fabsf(g_W2[base + n])) << 32) | (u64)(unsigned)(~(unsigned)n))
            : 0ull;
    }
    __syncthreads();

    const int nq = Np >> 1;
    const ulonglong2* K2 = (const ulonglong2*)keys;
    for (int k = tid; k < N; k += 256) {
        u64 mykey = keys[k];
        int rank = 0;
        #pragma unroll 4
        for (int j = 0; j < nq; j++) {
            ulonglong2 q = K2[j];
            rank += (int)(q.x > mykey) + (int)(q.y > mykey);
        }
        if (rank < nsel) {
            int src = base + k;
            int dst = row * nsel + rank;
            float w = g_W2[src];
            float c00 = g_C00[src], c01 = g_C01[src], c10 = g_C10[src], c11 = g_C11[src];
            g_SW[dst] = w;
            g_SPX[dst] = g_PX[src]; g_SPY[dst] = g_PY[src];
            g_SC00[dst] = c00; g_SC01[dst] = c01;
            g_SC10[dst] = c10; g_SC11[dst] = c11;
            float I = w * TWO_PI * fast_sqrt(fmaxf(c00 * c11 - c01 * c10, EPS));
            s_out[rank] = fabsf(I);
            s_out[32 + rank] = I;
        }
    }
    __syncthreads();
    if (tid == 0) {
        float tot = 0.0f, sg = 0.0f;
        for (int t = 0; t < nsel; t++) { tot += s_out[t]; sg += s_out[32 + t]; }
        g_TOT[row] = tot;
        if (do_final) g_SIG[row] = sg;
    }

    if (!do_final) return;

    // ---- fused finale: last block computes batchnorm + integrate + log_softmax ----
    if (tid == 0) {
        __threadfence();
        int t = atomicAdd(&g_tick, 1);
        s_last = (t == rows - 1) ? 1 : 0;
        if (s_last) g_tick = 0;
    }
    __syncthreads();
    if (!s_last) return;
    __threadfence();

    if (tid < 10) {
        float t = 0.0f;
        for (int b = 0; b < 32; b++) t += g_TOT[b * 10 + tid];
        scl[tid] = 1.0f / (t / 32.0f + EPS);
    }
    __syncthreads();
    for (int i = tid; i < 320; i += 256) logit[i] = g_SIG[i] * scl[i % 10];
    __syncthreads();
    if (tid < 32) {
        int b = tid;
        float mx = -INFINITY;
        for (int l = 0; l < 10; l++) mx = fmaxf(mx, logit[b * 10 + l]);
        float se = 0.0f;
        for (int l = 0; l < 10; l++) se += expf(logit[b * 10 + l] - mx);
        float lse = mx + logf(se);
        for (int l = 0; l < 10; l++) out[b * 10 + l] = logit[b * 10 + l] - lse;
    }
}

// ---------------- batchnorm(per_gaussian=False) apply ----------------
__global__ void k_bnapply(int Li, int B, int nsel) {
    int li = blockIdx.x;
    int tid = threadIdx.x;
    __shared__ float ssc;
    if (tid == 0) {
        float t = 0.0f;
        for (int b = 0; b < B; b++) t += g_TOT[b * Li + li];
        ssc = 1.0f / (t / (float)B + EPS);
    }
    __syncthreads();
    float sc = ssc;
    int tot = B * nsel;
    for (int i = tid; i < tot; i += blockDim.x) {
        int b = i / nsel, n = i % nsel;
        g_SW[(b * Li + li) * nsel + n] *= sc;
    }
}

extern "C" void kernel_launch(void* const* d_in, const int* in_sizes, int n_in,
                              void* d_out, int out_size) {
    const float* in_x = (const float*)d_in[0];
    const float* k1 = (const float*)d_in[1];
    const float* k2 = (const float*)d_in[2];
    const float* k3 = (const float*)d_in[3];
    const float* b1 = (const float*)d_in[4];
    const float* b2 = (const float*)d_in[5];
    const float* b3 = (const float*)d_in[6];
    float* out = (float*)d_out;

    k_bn_input<<<32, 64>>>(in_x);

    // ===== layer 1: B=32, Li=1, Nd=64, Lo=5, Nk=5 -> N=320, rows=160 =====
    {
        int B = 32, Li = 1, Nd = 64, Lo = 5, Nk = 5;
        int total = B * Lo * Li * Nd * Nk;
        int N = Li * Nd * Nk;
        int rows = B * Lo;
        int Np = (N + 1) & ~1;
        k_conv<<<(total + 255) / 256, 256>>>(k1, B, Li, Nd, Lo, Nk);
        dim3 eg((N + 127) / 128, rows);
        k_eval<<<eg, 128, Np * 24>>>(N, Lo, b1);
        k_topk<<<rows, 256>>>(N, 25, 0, rows, out);
        k_bnapply<<<Lo, 128>>>(Lo, B, 25);
    }

    // ===== layer 2: Li=5, Nd=25, Lo=6, Nk=5 -> N=625, rows=192 =====
    {
        int B = 32, Li = 5, Nd = 25, Lo = 6, Nk = 5;
        int total = B * Lo * Li * Nd * Nk;
        int N = Li * Nd * Nk;
        int rows = B * Lo;
        int Np = (N + 1) & ~1;
        k_conv<<<(total + 255) / 256, 256>>>(k2, B, Li, Nd, Lo, Nk);
        dim3 eg((N + 127) / 128, rows);
        k_eval<<<eg, 128, Np * 24>>>(N, Lo, b2);
        k_topk<<<rows, 256>>>(N, 12, 0, rows, out);
        k_bnapply<<<Lo, 128>>>(Lo, B, 12);
    }

    // ===== layer 3: Li=6, Nd=12, Lo=10, Nk=5 -> N=360, rows=320 (fused finale) =====
    {
        int B = 32, Li = 6, Nd = 12, Lo = 10, Nk = 5;
        int total = B * Lo * Li * Nd * Nk;
        int N = Li * Nd * Nk;
        int rows = B * Lo;
        int Np = (N + 1) & ~1;
        k_conv<<<(total + 255) / 256, 256>>>(k3, B, Li, Nd, Lo, Nk);
        dim3 eg((N + 127) / 128, rows);
        k_eval<<<eg, 128, Np * 24>>>(N, Lo, b3);
        k_topk<<<rows, 256>>>(N, 5, 1, rows, out);
    }
}

// round 6
// speedup vs baseline: 2.2298x; 1.5079x over previous
#include <cuda_runtime.h>
#include <math.h>

#define TWO_PI 6.283185307179586f
#define EPS 1e-6f
#define NEG_HALF_LOG2E (-0.7213475204444817f)

typedef unsigned long long u64;

// ---------------- device scratch ----------------
#define MAXM 120000
#define MAXS 4096
#define MAXROWS 320

__device__ float g_W[MAXM], g_PX[MAXM], g_PY[MAXM];
__device__ float g_EA[MAXM], g_EB[MAXM], g_EC[MAXM];
__device__ float g_C00[MAXM], g_C01[MAXM], g_C10[MAXM], g_C11[MAXM];
__device__ float g_W2[MAXM];

__device__ float g_SW[MAXS], g_SPX[MAXS], g_SPY[MAXS];
__device__ float g_SC00[MAXS], g_SC01[MAXS], g_SC10[MAXS], g_SC11[MAXS];

__device__ float g_TOT[MAXROWS], g_SIG[MAXROWS];
__device__ int g_tick = 0;

__device__ __forceinline__ float fast_exp2(float x) {
    float y; asm("ex2.approx.ftz.f32 %0, %1;" : "=f"(y) : "f"(x)); return y;
}
__device__ __forceinline__ float fast_sqrt(float x) {
    float y; asm("sqrt.approx.ftz.f32 %0, %1;" : "=f"(y) : "f"(x)); return y;
}
__device__ __forceinline__ float fast_rcp(float x) {
    float y; asm("rcp.approx.ftz.f32 %0, %1;" : "=f"(y) : "f"(x)); return y;
}

// ---- packed f32x2 helpers ----
__device__ __forceinline__ u64 pk2(float lo, float hi) {
    u64 r; asm("mov.b64 %0, {%1, %2};" : "=l"(r) : "f"(lo), "f"(hi)); return r;
}
__device__ __forceinline__ void upk2(u64 v, float& lo, float& hi) {
    asm("mov.b64 {%0, %1}, %2;" : "=f"(lo), "=f"(hi) : "l"(v));
}
__device__ __forceinline__ u64 add2(u64 a, u64 b) {
    u64 r; asm("add.rn.f32x2 %0, %1, %2;" : "=l"(r) : "l"(a), "l"(b)); return r;
}
__device__ __forceinline__ u64 mul2(u64 a, u64 b) {
    u64 r; asm("mul.rn.f32x2 %0, %1, %2;" : "=l"(r) : "l"(a), "l"(b)); return r;
}
__device__ __forceinline__ u64 fma2(u64 a, u64 b, u64 c) {
    u64 r; asm("fma.rn.f32x2 %0, %1, %2, %3;" : "=l"(r) : "l"(a), "l"(b), "l"(c)); return r;
}

// ---------------- conv with fused batchnorm prologue ----------------
// grid: (ceil(Lo*Li*Nd*Nk/256), B). first=1: input bn (per-gaussian, per-b);
// else: per-li scale from mean-over-batch of g_TOT.
__global__ void k_conv(const float* __restrict__ in_x, const float* __restrict__ kern,
                       int Li, int Nd, int Lo, int Nk, int first) {
    __shared__ float s_scl[8];
    __shared__ float s_red[64];
    const int tid = threadIdx.x;
    const int b = blockIdx.y;

    if (first) {
        if (tid < 64) {
            const float* m = in_x + (b * 64 + tid) * 7;
            float det = m[3] * m[6] - m[4] * m[5];
            s_red[tid] = fabsf(m[0] * TWO_PI * fast_sqrt(fmaxf(det, EPS)));
        }
        __syncthreads();
        if (tid < 32) {
            float v = s_red[tid] + s_red[tid + 32];
            for (int o = 16; o > 0; o >>= 1) v += __shfl_xor_sync(0xffffffffu, v, o);
            if (tid == 0) s_scl[0] = 1.0f / (v + EPS);
        }
        __syncthreads();
    } else {
        if (tid < Li * 32) {
            int li = tid >> 5, bb = tid & 31;
            float v = g_TOT[bb * Li + li];
            for (int o = 16; o > 0; o >>= 1) v += __shfl_xor_sync(0xffffffffu, v, o);
            if ((tid & 31) == 0) s_scl[li] = 1.0f / (v * (1.0f / 32.0f) + EPS);
        }
        __syncthreads();
    }

    int perB = Lo * Li * Nd * Nk;
    int i = blockIdx.x * 256 + tid;
    if (i >= perB) return;
    int nk = i % Nk; int t = i / Nk;
    int nd = t % Nd; t /= Nd;
    int li = t % Li; int lo = t / Li;

    int di = (b * Li + li) * Nd + nd;
    float wd, pdx, pdy, d00, d01, d10, d11;
    if (first) {
        const float* m = in_x + di * 7;
        wd = m[0] * s_scl[0]; pdx = m[1]; pdy = m[2];
        d00 = m[3]; d01 = m[4]; d10 = m[5]; d11 = m[6];
    } else {
        wd = g_SW[di] * s_scl[li];
        pdx = g_SPX[di]; pdy = g_SPY[di];
        d00 = g_SC00[di]; d01 = g_SC01[di]; d10 = g_SC10[di]; d11 = g_SC11[di];
    }

    const float* kp = kern + (((lo * Li + li) * Nk) + nk) * 7;
    float wk = kp[0], pkx = kp[1], pky = kp[2];
    float k00 = kp[3], k01 = kp[4], k10 = kp[5], k11 = kp[6];

    float s00 = d00 + k00, s01 = d01 + k01, s10 = d10 + k10, s11 = d11 + k11;
    float dd = d00 * d11 - d01 * d10;
    float dk = k00 * k11 - k01 * k10;
    float ds = s00 * s11 - s01 * s10;
    float inv = fast_rcp(fmaxf(ds, EPS));
    float ws = wd * wk * TWO_PI * fast_sqrt(dd * dk * inv);

    int o = (b * Lo + lo) * (Li * Nd * Nk) + (li * Nd + nd) * Nk + nk;
    g_W[o] = ws;
    g_PX[o] = pdx + pkx; g_PY[o] = pdy + pky;
    g_C00[o] = s00; g_C01[o] = s01; g_C10[o] = s10; g_C11[o] = s11;
    g_EA[o] = NEG_HALF_LOG2E * s11 * inv;
    g_EB[o] = -NEG_HALF_LOG2E * (s01 + s10) * inv;
    g_EC[o] = NEG_HALF_LOG2E * s00 * inv;
}

// ---------------- eval_at_centers + relu scaling (f32x2 packed) ----------------
__global__ void k_eval(int N, int Lo, const float* __restrict__ bias) {
    extern __shared__ __align__(16) float sh[];
    int Np = (N + 1) & ~1;
    int half = Np >> 1;
    float* sAf = sh;
    float* sBf = sh + 2 * Np;
    float* sCf = sh + 4 * Np;

    int row = blockIdx.y;
    int base = row * N;
    for (int n = threadIdx.x; n < Np; n += blockDim.x) {
        int j4 = (n >> 1) * 4 + (n & 1);
        if (n < N) {
            int g = base + n;
            sAf[j4] = g_PX[g]; sAf[j4 + 2] = g_PY[g];
            sBf[j4] = g_EA[g]; sBf[j4 + 2] = g_EB[g];
            sCf[j4] = g_EC[g]; sCf[j4 + 2] = g_W[g];
        } else {
            sAf[j4] = 0.0f; sAf[j4 + 2] = 0.0f;
            sBf[j4] = 0.0f; sBf[j4 + 2] = 0.0f;
            sCf[j4] = 0.0f; sCf[j4 + 2] = 0.0f;
        }
    }
    __syncthreads();

    int k = blockIdx.x * blockDim.x + threadIdx.x;
    if (k >= N) return;

    int k4 = (k >> 1) * 4 + (k & 1);
    float kx = sAf[k4], ky = sAf[k4 + 2];
    float wk = sCf[k4 + 2];
    u64 nkx2 = pk2(-kx, -kx);
    u64 nky2 = pk2(-ky, -ky);
    u64 acc = 0ull;

    const float4* sA = (const float4*)sAf;
    const float4* sB = (const float4*)sBf;
    const float4* sC = (const float4*)sCf;

    #pragma unroll 4
    for (int j = 0; j < half; j++) {
        float4 a = sA[j];
        float4 bq = sB[j];
        float4 c = sC[j];
        u64 px2 = *(const u64*)&a.x;  u64 py2 = *(const u64*)&a.z;
        u64 ea2 = *(const u64*)&bq.x; u64 eb2 = *(const u64*)&bq.z;
        u64 ec2 = *(const u64*)&c.x;  u64 w2p = *(const u64*)&c.z;

        u64 dx = add2(px2, nkx2);
        u64 dy = add2(py2, nky2);
        u64 u  = fma2(ea2, dx, mul2(eb2, dy));
        u64 md = fma2(dx, u, mul2(mul2(ec2, dy), dy));
        float m0, m1; upk2(md, m0, m1);
        u64 e = pk2(fast_exp2(m0), fast_exp2(m1));
        acc = fma2(w2p, e, acc);
    }

    float a0, a1; upk2(acc, a0, a1);
    float v = a0 + a1 + bias[row % Lo];
    float scale = fmaxf(v, 0.0f) * fast_rcp(fabsf(v) + EPS);
    g_W2[base + k] = wk * scale;
}

// ---------------- two-level rank top-k: one block per row ----------------
// block = 32*nchunks threads (chunk width 64, one warp per chunk).
// key = (|w2| bits << 32) | ~k : unique, descending order == jax top_k order.
// Level 1: rank within own chunk (warp-broadcast smem reads); local rank >= nsel
//   implies global rank >= nsel -> discard. Level 2: exact rank among candidates
//   equals global rank for the true top-nsel.
__global__ void k_topk(int N, int nchunks, int nsel, int do_final, int rows,
                       float* __restrict__ out) {
    const int tid = threadIdx.x;
    const int row = blockIdx.x;
    const int base = row * N;
    const int NC = nchunks * 64;

    __shared__ __align__(16) u64 keys[640];
    __shared__ __align__(16) u64 sCand[136];
    __shared__ int s_cnt;
    __shared__ float s_out[64];
    __shared__ int s_last;
    __shared__ float scl[10];
    __shared__ float logit[320];

    if (tid == 0) s_cnt = 0;
    for (int n = tid; n < NC; n += blockDim.x) {
        keys[n] = (n < N)
            ? (((u64)__float_as_uint(fabsf(g_W2[base + n])) << 32) | (u64)(unsigned)(~(unsigned)n))
            : 0ull;
    }
    __syncthreads();

    // ---- level 1: per-warp chunk rank ----
    {
        int w = tid >> 5, lane = tid & 31;
        int kb = w << 6;
        u64 k0 = keys[kb + lane];
        u64 k1 = keys[kb + lane + 32];
        int r0 = 0, r1 = 0;
        const ulonglong2* Q = (const ulonglong2*)(keys + kb);
        #pragma unroll 8
        for (int j = 0; j < 32; j++) {
            ulonglong2 q = Q[j];
            r0 += (int)(q.x > k0) + (int)(q.y > k0);
            r1 += (int)(q.x > k1) + (int)(q.y > k1);
        }
        if (kb + lane < N && r0 < nsel)      { int s = atomicAdd(&s_cnt, 1); sCand[s] = k0; }
        if (kb + lane + 32 < N && r1 < nsel) { int s = atomicAdd(&s_cnt, 1); sCand[s] = k1; }
    }
    __syncthreads();
    int m = s_cnt;
    if (tid == 0 && (m & 1)) sCand[m] = 0ull;  // pad for u64x2 loads
    __syncthreads();

    // ---- level 2: exact rank among candidates ----
    {
        int mq = (m + 1) >> 1;
        const ulonglong2* Q = (const ulonglong2*)sCand;
        for (int i = tid; i < m; i += blockDim.x) {
            u64 mykey = sCand[i];
            int rank = 0;
            #pragma unroll 4
            for (int j = 0; j < mq; j++) {
                ulonglong2 q = Q[j];
                rank += (int)(q.x > mykey) + (int)(q.y > mykey);
            }
            if (rank < nsel) {
                int n = (int)(~(unsigned)mykey);
                int src = base + n;
                int dst = row * nsel + rank;
                float wv = g_W2[src];
                float c00 = g_C00[src], c01 = g_C01[src], c10 = g_C10[src], c11 = g_C11[src];
                g_SW[dst] = wv;
                g_SPX[dst] = g_PX[src]; g_SPY[dst] = g_PY[src];
                g_SC00[dst] = c00; g_SC01[dst] = c01;
                g_SC10[dst] = c10; g_SC11[dst] = c11;
                float I = wv * TWO_PI * fast_sqrt(fmaxf(c00 * c11 - c01 * c10, EPS));
                s_out[rank] = fabsf(I);
                s_out[32 + rank] = I;
            }
        }
    }
    __syncthreads();
    if (tid == 0) {
        float tot = 0.0f, sg = 0.0f;
        for (int t = 0; t < nsel; t++) { tot += s_out[t]; sg += s_out[32 + t]; }
        g_TOT[row] = tot;
        if (do_final) g_SIG[row] = sg;
    }

    if (!do_final) return;

    // ---- fused finale: last block does batchnorm + integrate + log_softmax ----
    if (tid == 0) {
        __threadfence();
        int t = atomicAdd(&g_tick, 1);
        s_last = (t == rows - 1) ? 1 : 0;
        if (s_last) g_tick = 0;
    }
    __syncthreads();
    if (!s_last) return;
    __threadfence();

    if (tid < 10) {
        float t = 0.0f;
        for (int b = 0; b < 32; b++) t += g_TOT[b * 10 + tid];
        scl[tid] = 1.0f / (t / 32.0f + EPS);
    }
    __syncthreads();
    for (int i = tid; i < 320; i += blockDim.x) logit[i] = g_SIG[i] * scl[i % 10];
    __syncthreads();
    if (tid < 32) {
        int b = tid;
        float mx = -INFINITY;
        for (int l = 0; l < 10; l++) mx = fmaxf(mx, logit[b * 10 + l]);
        float se = 0.0f;
        for (int l = 0; l < 10; l++) se += expf(logit[b * 10 + l] - mx);
        float lse = mx + logf(se);
        for (int l = 0; l < 10; l++) out[b * 10 + l] = logit[b * 10 + l] - lse;
    }
}

extern "C" void kernel_launch(void* const* d_in, const int* in_sizes, int n_in,
                              void* d_out, int out_size) {
    const float* in_x = (const float*)d_in[0];
    const float* k1 = (const float*)d_in[1];
    const float* k2 = (const float*)d_in[2];
    const float* k3 = (const float*)d_in[3];
    const float* b1 = (const float*)d_in[4];
    const float* b2 = (const float*)d_in[5];
    const float* b3 = (const float*)d_in[6];
    float* out = (float*)d_out;
    const int B = 32;

    // ===== layer 1: Li=1, Nd=64, Lo=5, Nk=5 -> N=320, rows=160, nsel=25 =====
    {
        int Li = 1, Nd = 64, Lo = 5, Nk = 5;
        int N = Li * Nd * Nk, rows = B * Lo, perB = Lo * N;
        int Np = (N + 1) & ~1, nch = (N + 63) / 64;
        k_conv<<<dim3((perB + 255) / 256, B), 256>>>(in_x, k1, Li, Nd, Lo, Nk, 1);
        k_eval<<<dim3((N + 127) / 128, rows), 128, Np * 24>>>(N, Lo, b1);
        k_topk<<<rows, 32 * nch>>>(N, nch, 25, 0, rows, out);
    }

    // ===== layer 2: Li=5, Nd=25, Lo=6, Nk=5 -> N=625, rows=192, nsel=12 =====
    {
        int Li = 5, Nd = 25, Lo = 6, Nk = 5;
        int N = Li * Nd * Nk, rows = B * Lo, perB = Lo * N;
        int Np = (N + 1) & ~1, nch = (N + 63) / 64;
        k_conv<<<dim3((perB + 255) / 256, B), 256>>>(in_x, k2, Li, Nd, Lo, Nk, 0);
        k_eval<<<dim3((N + 127) / 128, rows), 128, Np * 24>>>(N, Lo, b2);
        k_topk<<<rows, 32 * nch>>>(N, nch, 12, 0, rows, out);
    }

    // ===== layer 3: Li=6, Nd=12, Lo=10, Nk=5 -> N=360, rows=320, nsel=5 =====
    {
        int Li = 6, Nd = 12, Lo = 10, Nk = 5;
        int N = Li * Nd * Nk, rows = B * Lo, perB = Lo * N;
        int Np = (N + 1) & ~1, nch = (N + 63) / 64;
        k_conv<<<dim3((perB + 255) / 256, B), 256>>>(in_x, k3, Li, Nd, Lo, Nk, 0);
        k_eval<<<dim3((N + 127) / 128, rows), 128, Np * 24>>>(N, Lo, b3);
        k_topk<<<rows, 32 * nch>>>(N, nch, 5, 1, rows, out);
    }
}